// round 2
// baseline (speedup 1.0000x reference)
#include <cuda_runtime.h>
#include <cstdint>

// Problem shape (fixed by the dataset)
#define TOK   32768          // 4 * 8192 tokens
#define HDIM  4096
#define NE    64             // experts
#define TOPK  2

// Tiling
#define BM    128            // tokens per CTA
#define BK    32             // k-slice
#define NT    128            // threads per CTA
#define KT    (HDIM / BK)    // 128 k-tiles

// Packed fp32x2 ops (sm_100+), kept in inline PTX so the compiler cannot
// reassociate or contract them (accumulation order is load-bearing for
// top-k tie correctness).
#define FMA2(d, a, b) \
    asm("fma.rn.f32x2 %0, %1, %2, %0;" : "+l"(d) : "l"(a), "l"(b))
#define MUL2(d, a, b) \
    asm("mul.rn.f32x2 %0, %1, %2;" : "=l"(d) : "l"(a), "l"(b))
#define ADD2(d, s) \
    asm("add.rn.f32x2 %0, %0, %1;" : "+l"(d) : "l"(s))
// Duplicate a scalar float into both halves of a 64-bit pair
#define DUP2(d, s) \
    asm("mov.b64 %0, {%1, %1};" : "=l"(d) : "r"(s))
// Unpack a 64-bit pair
#define UNPK2(lo, hi, p) \
    asm("mov.b64 {%0, %1}, %2;" : "=r"(lo), "=r"(hi) : "l"(p))

__global__ void __launch_bounds__(NT, 2)
moe_gate_kernel(const float* __restrict__ X,   // [TOK, HDIM]
                const float* __restrict__ W,   // [NE, HDIM]
                float* __restrict__ out)       // [2*TOK idx | 2*TOK weight] as f32
{
    // smem: x tile (swizzled, [BK][BM] = 16KB) + w tile (swizzled, [BK][NE] = 8KB),
    // later overlaid by logits[BM][65] (33280B). One buffer, max size.
    __shared__ __align__(16) float smem[BM * 65];     // 8320 floats = 33280 B
    float* xs = smem;                 // BK*BM = 4096 floats
    float* ws = smem + BK * BM;       // BK*NE = 2048 floats
    float* lg = smem;                 // logits overlay [BM][65]

    const int tid  = threadIdx.x;
    const int tc   = tid >> 4;        // 0..7  -> expert group (8 experts)
    const int tr   = tid & 15;        // 0..15 -> token lanes
    const int tok0 = blockIdx.x * BM;

    const float* Xg = X + (size_t)tok0 * HDIM;

    // ---- staging registers (global -> reg -> smem pipeline) ----
    float4 xa[8];
    float4 wa[4];

    // ---- accumulators: acc[e][j] holds (token t0, token t0+1) pair for expert e
    // tokens of this thread: t(j,p) = j*32 + tr*2 + p   (j=0..3, p=0..1)
    // experts of this thread: e(i) = tc*8 + i           (i=0..7)
    // Two-level summation: tp = fresh per-k-tile partial; acc += tp per tile.
    uint64_t acc[8][4];
    uint64_t tp[8][4];
#pragma unroll
    for (int i = 0; i < 8; ++i)
#pragma unroll
        for (int j = 0; j < 4; ++j) acc[i][j] = 0ull;

    // ---------------- stage tile 0 ----------------
    {
        const int kbase = 0;
#pragma unroll
        for (int it = 0; it < 8; ++it) {
            int f = it * NT + tid;
            int t = f >> 3, k4 = f & 7;
            xa[it] = *(const float4*)(Xg + (size_t)t * HDIM + kbase + k4 * 4);
        }
#pragma unroll
        for (int it = 0; it < 4; ++it) {
            int f = it * NT + tid;
            int e = f >> 3, k4 = f & 7;
            wa[it] = *(const float4*)(W + (size_t)e * HDIM + kbase + k4 * 4);
        }
    }

    const int xo = (tr & 3) << 1;     // token offset-in-group (even)
    const int g0 = tr >> 2;           // token group base

    for (int kt = 0; kt < KT; ++kt) {
        __syncthreads();              // previous compute done reading smem

        // ---- commit staged registers to swizzled smem ----
#pragma unroll
        for (int it = 0; it < 8; ++it) {
            int f = it * NT + tid;
            int t = f >> 3, k4 = f & 7;
            int tg = t >> 3, tl = t & 7;
            float v[4] = {xa[it].x, xa[it].y, xa[it].z, xa[it].w};
#pragma unroll
            for (int c = 0; c < 4; ++c) {
                int k = k4 * 4 + c;
                xs[k * BM + (((tg ^ (k & 15)) << 3) | tl)] = v[c];
            }
        }
#pragma unroll
        for (int it = 0; it < 4; ++it) {
            int f = it * NT + tid;
            int e = f >> 3, k4 = f & 7;
            int eg = e >> 3, el = e & 7;
            float v[4] = {wa[it].x, wa[it].y, wa[it].z, wa[it].w};
#pragma unroll
            for (int c = 0; c < 4; ++c) {
                int k = k4 * 4 + c;
                ws[k * NE + (((eg ^ (k & 7)) << 3) | el)] = v[c];
            }
        }
        __syncthreads();

        // ---- prefetch next tile into registers (overlaps with compute) ----
        if (kt + 1 < KT) {
            const int kbase = (kt + 1) * BK;
#pragma unroll
            for (int it = 0; it < 8; ++it) {
                int f = it * NT + tid;
                int t = f >> 3, k4 = f & 7;
                xa[it] = *(const float4*)(Xg + (size_t)t * HDIM + kbase + k4 * 4);
            }
#pragma unroll
            for (int it = 0; it < 4; ++it) {
                int f = it * NT + tid;
                int e = f >> 3, k4 = f & 7;
                wa[it] = *(const float4*)(W + (size_t)e * HDIM + kbase + k4 * 4);
            }
        }

        // ---- compute: 32 k-steps, 8x8 register tile via f32x2 ----
        // kk = 0 peeled: tp = x*w (fresh tile partial, no zero-init needed)
        {
            const int kk = 0;
            uint64_t xv[4];
#pragma unroll
            for (int j = 0; j < 4; ++j) {
                int idx = kk * BM + ((((4 * j + g0) ^ (kk & 15)) << 3) | xo);
                xv[j] = *reinterpret_cast<const uint64_t*>(&xs[idx]);
            }
            int wbase = kk * NE + ((tc ^ (kk & 7)) << 3);
            float4 w0 = *(const float4*)(&ws[wbase]);
            float4 w1 = *(const float4*)(&ws[wbase + 4]);
            uint64_t wd[8];
            DUP2(wd[0], __float_as_uint(w0.x));
            DUP2(wd[1], __float_as_uint(w0.y));
            DUP2(wd[2], __float_as_uint(w0.z));
            DUP2(wd[3], __float_as_uint(w0.w));
            DUP2(wd[4], __float_as_uint(w1.x));
            DUP2(wd[5], __float_as_uint(w1.y));
            DUP2(wd[6], __float_as_uint(w1.z));
            DUP2(wd[7], __float_as_uint(w1.w));
#pragma unroll
            for (int i = 0; i < 8; ++i)
#pragma unroll
                for (int j = 0; j < 4; ++j)
                    MUL2(tp[i][j], xv[j], wd[i]);
        }
#pragma unroll 15
        for (int kk = 1; kk < BK; ++kk) {
            uint64_t xv[4];
#pragma unroll
            for (int j = 0; j < 4; ++j) {
                int idx = kk * BM + ((((4 * j + g0) ^ (kk & 15)) << 3) | xo);
                xv[j] = *reinterpret_cast<const uint64_t*>(&xs[idx]);
            }
            int wbase = kk * NE + ((tc ^ (kk & 7)) << 3);
            float4 w0 = *(const float4*)(&ws[wbase]);
            float4 w1 = *(const float4*)(&ws[wbase + 4]);
            uint64_t wd[8];
            DUP2(wd[0], __float_as_uint(w0.x));
            DUP2(wd[1], __float_as_uint(w0.y));
            DUP2(wd[2], __float_as_uint(w0.z));
            DUP2(wd[3], __float_as_uint(w0.w));
            DUP2(wd[4], __float_as_uint(w1.x));
            DUP2(wd[5], __float_as_uint(w1.y));
            DUP2(wd[6], __float_as_uint(w1.z));
            DUP2(wd[7], __float_as_uint(w1.w));
#pragma unroll
            for (int i = 0; i < 8; ++i)
#pragma unroll
                for (int j = 0; j < 4; ++j)
                    FMA2(tp[i][j], xv[j], wd[i]);
        }
        // fold tile partial into the long accumulator (one rounded add per tile)
#pragma unroll
        for (int i = 0; i < 8; ++i)
#pragma unroll
            for (int j = 0; j < 4; ++j)
                ADD2(acc[i][j], tp[i][j]);
    }

    // ---------------- epilogue: scatter logits to smem ----------------
    __syncthreads();   // done with xs/ws; reuse as logits
#pragma unroll
    for (int i = 0; i < 8; ++i) {
        int e = tc * 8 + i;
#pragma unroll
        for (int j = 0; j < 4; ++j) {
            uint32_t lo, hi;
            UNPK2(lo, hi, acc[i][j]);
            int t0 = j * 32 + tr * 2;
            lg[t0 * 65 + e]       = __uint_as_float(lo);
            lg[(t0 + 1) * 65 + e] = __uint_as_float(hi);
        }
    }
    __syncthreads();

    // ---------------- per-token softmax + top-2 (1 thread / token) ----------------
    {
        const int t = tid;                 // 128 threads <-> 128 tokens
        const float* row = lg + t * 65;    // stride 65 -> conflict-free

        float mx = row[0];
#pragma unroll 8
        for (int e = 1; e < NE; ++e) mx = fmaxf(mx, row[e]);

        float sum = 0.0f;
        float b1 = -3.4e38f, b2 = -3.4e38f;
        int   i1 = 0, i2 = 0;
#pragma unroll 8
        for (int e = 0; e < NE; ++e) {
            float l = row[e];
            sum += expf(l - mx);
            if (l > b1)      { b2 = b1; i2 = i1; b1 = l; i1 = e; }
            else if (l > b2) { b2 = l; i2 = e; }
        }
        float inv = 1.0f / sum;
        int gt = tok0 + t;
        // reference returns (topk_idx, topk_weight): idx first, then weights
        out[2 * gt]               = (float)i1;
        out[2 * gt + 1]           = (float)i2;
        out[2 * TOK + 2 * gt]     = expf(b1 - mx) * inv;
        out[2 * TOK + 2 * gt + 1] = expf(b2 - mx) * inv;
    }
}

extern "C" void kernel_launch(void* const* d_in, const int* in_sizes, int n_in,
                              void* d_out, int out_size)
{
    const float* X = (const float*)d_in[0];   // hidden_states [4,8192,4096] f32
    const float* W = (const float*)d_in[1];   // weight [64,4096] f32
    float* out = (float*)d_out;
    moe_gate_kernel<<<TOK / BM, NT>>>(X, W, out);
}

// round 4
// speedup vs baseline: 1.3518x; 1.3518x over previous
#include <cuda_runtime.h>
#include <cuda_bf16.h>
#include <cstdint>

// ---------------- problem shape ----------------
#define TOK   32768
#define HDIM  4096
#define NE    64
#define BM    128            // tokens per CTA
#define BK    32             // k per chunk
#define NCH   128            // HDIM / BK
#define NT    128            // threads (4 warps)
#define TAU   1e-4f

// smem layout (words): per buffer: XH[128][20] XL[128][20] WH[64][20] WL[64][20]
#define ROWW   20                        // 16 data words (32 bf16) + 4 pad
#define XWORDS (BM * ROWW)               // 2560
#define WWORDS (NE * ROWW)               // 1280
#define BUFW   (2 * XWORDS + 2 * WWORDS) // 7680 words
#define BUFB   (BUFW * 4)                // 30720 bytes
#define WOFFB  (2 * XWORDS * 4)          // 20480 byte offset of W planes
#define SMEMB  (2 * BUFB)                // 61440 bytes

// ---------------- device globals (no allocs allowed) ----------------
__device__ uint32_t g_w[NCH * 2 * WWORDS];   // [chunk][plane h/l][expert][kp(+pad)]
__device__ int g_flag_count;
__device__ int g_flag_list[TOK];

// ---------------- helpers ----------------
__device__ __forceinline__ uint32_t s2u(const void* p) {
    uint32_t a;
    asm("{ .reg .u64 t; cvta.to.shared.u64 t, %1; cvt.u32.u64 %0, t; }" : "=r"(a) : "l"(p));
    return a;
}

// pack {lo=f0, hi=f1} as bf16x2 (round-to-nearest)
__device__ __forceinline__ uint32_t cvt2(float f1, float f0) {
    uint32_t d;
    asm("cvt.rn.bf16x2.f32 %0, %1, %2;" : "=r"(d) : "f"(f1), "f"(f0));
    return d;
}
// split (f0,f1) into high-pair + low-residual-pair
__device__ __forceinline__ void splitpair(float f0, float f1, uint32_t& h, uint32_t& l) {
    h = cvt2(f1, f0);
    float h0 = __uint_as_float(h << 16);
    float h1 = __uint_as_float(h & 0xFFFF0000u);
    l = cvt2(f1 - h1, f0 - h0);
}

__device__ __forceinline__ void ldsm4(uint32_t* r, uint32_t addr) {
    asm volatile("ldmatrix.sync.aligned.m8n8.x4.shared.b16 {%0,%1,%2,%3}, [%4];"
                 : "=r"(r[0]), "=r"(r[1]), "=r"(r[2]), "=r"(r[3]) : "r"(addr));
}

__device__ __forceinline__ void mma16816(float* c, const uint32_t* a,
                                         uint32_t b0, uint32_t b1) {
    asm("mma.sync.aligned.m16n8k16.row.col.f32.bf16.bf16.f32 "
        "{%0,%1,%2,%3}, {%4,%5,%6,%7}, {%8,%9}, {%0,%1,%2,%3};"
        : "+f"(c[0]), "+f"(c[1]), "+f"(c[2]), "+f"(c[3])
        : "r"(a[0]), "r"(a[1]), "r"(a[2]), "r"(a[3]), "r"(b0), "r"(b1));
}

// ---------------- prep: W fp32 -> (h,l) bf16-pair planes, padded layout ----------------
__global__ void prep_w(const float* __restrict__ W) {
    int id = blockIdx.x * 256 + threadIdx.x;
    if (id == 0) g_flag_count = 0;
    if (id >= NCH * NE) return;
    int c = id >> 6, e = id & 63;
    const float* src = W + (size_t)e * HDIM + c * BK;
    uint32_t* dh = g_w + (c * 2 + 0) * WWORDS + e * ROWW;
    uint32_t* dl = g_w + (c * 2 + 1) * WWORDS + e * ROWW;
#pragma unroll
    for (int kp = 0; kp < 16; ++kp) {
        uint32_t h, l;
        splitpair(src[2 * kp], src[2 * kp + 1], h, l);
        dh[kp] = h;
        dl[kp] = l;
    }
#pragma unroll
    for (int kp = 16; kp < 20; ++kp) { dh[kp] = 0u; dl[kp] = 0u; }
}

// ---------------- main: bf16x2 HMMA GEMM + fused softmax/top2 ----------------
__global__ void __launch_bounds__(NT, 2)
moe_gate_mma(const float* __restrict__ X, float* __restrict__ out) {
    extern __shared__ char smem_raw[];
    const uint32_t sbase = s2u(smem_raw);

    const int tid  = threadIdx.x;
    const int lane = tid & 31, wid = tid >> 5;
    const int lrow = lane & 15, lkh = lane >> 4;
    const int tok0 = blockIdx.x * BM;
    const float* Xg = X + (size_t)tok0 * HDIM;

    // ldmatrix per-lane base addresses (bytes)
    const uint32_t aAddr = sbase + ((wid * 32 + lrow) * ROWW + lkh * 4) * 4;
    const uint32_t bAddr = sbase + WOFFB + (lrow * ROWW + lkh * 4) * 4;

    float acc[2][8][4];
#pragma unroll
    for (int mt = 0; mt < 2; ++mt)
#pragma unroll
        for (int nt = 0; nt < 8; ++nt)
#pragma unroll
            for (int q = 0; q < 4; ++q) acc[mt][nt][q] = 0.0f;

    float4 xa[8];
    uint4  wv[5];

    // ---- stage chunk 0 into buffer 0 ----
    {
#pragma unroll
        for (int it = 0; it < 8; ++it) {
            int f = it * NT + tid;
            int row = f >> 3, k4 = f & 7;
            xa[it] = *(const float4*)(Xg + (size_t)row * HDIM + k4 * 4);
        }
        const uint4* wsrc = (const uint4*)(g_w);
#pragma unroll
        for (int it = 0; it < 5; ++it) wv[it] = wsrc[it * NT + tid];

#pragma unroll
        for (int it = 0; it < 8; ++it) {
            int f = it * NT + tid;
            int row = f >> 3, k4 = f & 7;
            uint32_t h0, l0, h1, l1;
            splitpair(xa[it].x, xa[it].y, h0, l0);
            splitpair(xa[it].z, xa[it].w, h1, l1);
            int w = row * ROWW + k4 * 2;
            *(uint2*)(smem_raw + w * 4)                  = make_uint2(h0, h1);
            *(uint2*)(smem_raw + (XWORDS + w) * 4)       = make_uint2(l0, l1);
        }
#pragma unroll
        for (int it = 0; it < 5; ++it) {
            int idx = it * NT + tid;
            *(uint4*)(smem_raw + WOFFB + idx * 16) = wv[it];
        }
    }
    __syncthreads();

    // ---- main loop over 128 chunks ----
    for (int c = 0; c < NCH; ++c) {
        const uint32_t bufR = (uint32_t)(c & 1) * BUFB;
        const uint32_t bufW = (uint32_t)((c + 1) & 1) * BUFB;
        const bool more = (c + 1 < NCH);

        // prefetch next chunk (gmem -> regs), overlaps mma below
        if (more) {
            const int kb = (c + 1) * BK;
#pragma unroll
            for (int it = 0; it < 8; ++it) {
                int f = it * NT + tid;
                int row = f >> 3, k4 = f & 7;
                xa[it] = *(const float4*)(Xg + (size_t)row * HDIM + kb + k4 * 4);
            }
            const uint4* wsrc = (const uint4*)(g_w + (size_t)(c + 1) * 2 * WWORDS);
#pragma unroll
            for (int it = 0; it < 5; ++it) wv[it] = wsrc[it * NT + tid];
        }

        // mma on current buffer: 2 ksteps x (2 mtiles x 8 ntiles) x 3 passes
#pragma unroll
        for (int ks = 0; ks < 2; ++ks) {
            uint32_t Ah[2][4], Al[2][4];
#pragma unroll
            for (int mt = 0; mt < 2; ++mt) {
                ldsm4(Ah[mt], aAddr + bufR + 0 * XWORDS * 4 + mt * 16 * ROWW * 4 + ks * 32);
                ldsm4(Al[mt], aAddr + bufR + 1 * XWORDS * 4 + mt * 16 * ROWW * 4 + ks * 32);
            }
#pragma unroll
            for (int np = 0; np < 4; ++np) {
                uint32_t Bh[4], Bl[4];
                ldsm4(Bh, bAddr + bufR + 0 * WWORDS * 4 + np * 16 * ROWW * 4 + ks * 32);
                ldsm4(Bl, bAddr + bufR + 1 * WWORDS * 4 + np * 16 * ROWW * 4 + ks * 32);
#pragma unroll
                for (int sub = 0; sub < 2; ++sub) {
#pragma unroll
                    for (int mt = 0; mt < 2; ++mt) {
                        float* cc = acc[mt][np * 2 + sub];
                        mma16816(cc, Ah[mt], Bh[sub], Bh[2 + sub]);   // h*h
                        mma16816(cc, Ah[mt], Bl[sub], Bl[2 + sub]);   // h*l
                        mma16816(cc, Al[mt], Bh[sub], Bh[2 + sub]);   // l*h
                    }
                }
            }
        }

        // convert + store next chunk into the other buffer
        if (more) {
#pragma unroll
            for (int it = 0; it < 8; ++it) {
                int f = it * NT + tid;
                int row = f >> 3, k4 = f & 7;
                uint32_t h0, l0, h1, l1;
                splitpair(xa[it].x, xa[it].y, h0, l0);
                splitpair(xa[it].z, xa[it].w, h1, l1);
                int w = row * ROWW + k4 * 2;
                *(uint2*)(smem_raw + bufW + w * 4)            = make_uint2(h0, h1);
                *(uint2*)(smem_raw + bufW + (XWORDS + w) * 4) = make_uint2(l0, l1);
            }
#pragma unroll
            for (int it = 0; it < 5; ++it) {
                int idx = it * NT + tid;
                *(uint4*)(smem_raw + bufW + WOFFB + idx * 16) = wv[it];
            }
        }
        __syncthreads();
    }

    // ---- scatter logits into smem overlay lg[128][65] ----
    float* lg = (float*)smem_raw;
    const int g = lane >> 2, tig = lane & 3;
#pragma unroll
    for (int mt = 0; mt < 2; ++mt) {
#pragma unroll
        for (int nt = 0; nt < 8; ++nt) {
            int r0 = wid * 32 + mt * 16 + g;
            int e0 = nt * 8 + tig * 2;
            lg[r0 * 65 + e0]           = acc[mt][nt][0];
            lg[r0 * 65 + e0 + 1]       = acc[mt][nt][1];
            lg[(r0 + 8) * 65 + e0]     = acc[mt][nt][2];
            lg[(r0 + 8) * 65 + e0 + 1] = acc[mt][nt][3];
        }
    }
    __syncthreads();

    // ---- per-token softmax + top-3 + near-tie flag (1 thread / token) ----
    {
        const int t = tid;
        const float* row = lg + t * 65;
        float mx = row[0];
#pragma unroll 8
        for (int e = 1; e < NE; ++e) mx = fmaxf(mx, row[e]);
        float sum = 0.0f;
        float s1 = -3.4e38f, s2 = -3.4e38f, s3 = -3.4e38f;
        int i1 = 0, i2 = 0;
#pragma unroll 8
        for (int e = 0; e < NE; ++e) {
            float l = row[e];
            sum += expf(l - mx);
            if (l > s1)      { s3 = s2; s2 = s1; i2 = i1; s1 = l; i1 = e; }
            else if (l > s2) { s3 = s2; s2 = l; i2 = e; }
            else if (l > s3) { s3 = l; }
        }
        float inv = 1.0f / sum;
        int gt = tok0 + t;
        out[2 * gt]               = (float)i1;
        out[2 * gt + 1]           = (float)i2;
        out[2 * TOK + 2 * gt]     = expf(s1 - mx) * inv;
        out[2 * TOK + 2 * gt + 1] = expf(s2 - mx) * inv;
        if ((s1 - s2 < TAU) || (s2 - s3 < TAU)) {
            int sl = atomicAdd(&g_flag_count, 1);
            if (sl < TOK) g_flag_list[sl] = gt;
        }
    }
}

// ---------------- cleanup: fp64 recompute of near-tie tokens ----------------
__global__ void cleanup_kernel(const float* __restrict__ X, const float* __restrict__ W,
                               float* __restrict__ out) {
    __shared__ double sred[128];
    __shared__ double lgs[64];
    int nf = g_flag_count;
    if (nf > TOK) nf = TOK;
    for (int i = blockIdx.x; i < nf; i += gridDim.x) {
        int t = g_flag_list[i];
        int e  = threadIdx.x & 63;
        int kh = threadIdx.x >> 6;
        const float* xr = X + (size_t)t * HDIM + kh * 2048;
        const float* wr = W + (size_t)e * HDIM + kh * 2048;
        double a = 0.0;
        for (int k = 0; k < 2048; ++k)
            a += (double)xr[k] * (double)wr[k];
        sred[threadIdx.x] = a;
        __syncthreads();
        if (threadIdx.x < 64) lgs[threadIdx.x] = sred[threadIdx.x] + sred[threadIdx.x + 64];
        __syncthreads();
        if (threadIdx.x == 0) {
            double mx = lgs[0];
            for (int q = 1; q < NE; ++q) if (lgs[q] > mx) mx = lgs[q];
            double sum = 0.0;
            double s1 = -1e300, s2 = -1e300;
            int i1 = 0, i2 = 0;
            for (int q = 0; q < NE; ++q) {
                double l = lgs[q];
                sum += exp(l - mx);
                if (l > s1)      { s2 = s1; i2 = i1; s1 = l; i1 = q; }
                else if (l > s2) { s2 = l; i2 = q; }
            }
            double inv = 1.0 / sum;
            out[2 * t]               = (float)i1;
            out[2 * t + 1]           = (float)i2;
            out[2 * TOK + 2 * t]     = (float)(exp(s1 - mx) * inv);
            out[2 * TOK + 2 * t + 1] = (float)(exp(s2 - mx) * inv);
        }
        __syncthreads();
    }
}

// ---------------- launch ----------------
extern "C" void kernel_launch(void* const* d_in, const int* in_sizes, int n_in,
                              void* d_out, int out_size) {
    const float* X = (const float*)d_in[0];
    const float* W = (const float*)d_in[1];
    float* out = (float*)d_out;

    static bool once = []() {
        cudaFuncSetAttribute(moe_gate_mma, cudaFuncAttributeMaxDynamicSharedMemorySize,
                             SMEMB);
        return true;
    }();
    (void)once;

    prep_w<<<(NCH * NE + 255) / 256, 256>>>(W);
    moe_gate_mma<<<TOK / BM, NT, SMEMB>>>(X, out);
    cleanup_kernel<<<128, 128>>>(X, W, out);
}